// round 1
// baseline (speedup 1.0000x reference)
#include <cuda_runtime.h>
#include <cuda_bf16.h>

// Problem constants
#define BB   16
#define CC   256      // channels per image (input has 2*CC)
#define HH   64
#define WW   192
#define DD   25       // disparities 0..24
#define HWs  (HH*WW)              // 12288
#define CHW  (512*HH*WW)          // per-batch input stride: 6291456
#define X2OFF ((size_t)CC*HWs)    // offset from x1 to x2: 3145728

// Kernel-1 tiling
#define CK    4       // channels per smem chunk
#define ROWSK 4       // h-rows per block
#define TPB1  192     // 48 thr/row * 4 rows
#define NROWS (CK*ROWSK)          // 16 smem rows
#define X2W   (WW+24)             // 216: 24-left zero pad

// scratch: corr[b][d][h][w]
__device__ float g_corr[(size_t)BB*DD*HH*WW];

__global__ __launch_bounds__(TPB1, 2)
void corr_kernel(const float* __restrict__ in) {
    __shared__ float x1s[NROWS * WW];    // 16*192*4 = 12.3 KB
    __shared__ float x2s[NROWS * X2W];   // 16*216*4 = 13.8 KB

    const int t  = threadIdx.x;
    const int b  = blockIdx.y;
    const int h0 = blockIdx.x * ROWSK;

    const int rr = t / 48;        // my h-row within the block (0..3)
    const int j  = t - rr * 48;   // my w-quad (0..47) -> w0 = 4*j
    const int w0 = 4 * j;

    // zero the 24-column left pad of x2s once (never overwritten)
    for (int idx = t; idx < NROWS * 24; idx += TPB1) {
        int row = idx / 24;
        int col = idx - row * 24;
        x2s[row * X2W + col] = 0.0f;
    }

    float4 acc[DD];
    #pragma unroll
    for (int i = 0; i < DD; i++) acc[i] = make_float4(0.f, 0.f, 0.f, 0.f);

    const float* base = in + (size_t)b * CHW + (size_t)h0 * WW;

    for (int ch = 0; ch < CC / CK; ch++) {
        __syncthreads();
        // ---- load CK channels x ROWSK rows of x1 and x2 (float4, coalesced)
        const float* p1 = base + (size_t)ch * CK * HWs;
        #pragma unroll
        for (int it = 0; it < 4; it++) {
            int q   = it * TPB1 + t;        // 0..767 float4 slots
            int row = q / 48;               // 0..15  (= c_local*4 + r)
            int col = (q - row * 48) * 4;   // 0..188
            int cl  = row >> 2;
            int r   = row & 3;
            size_t goff = (size_t)cl * HWs + (size_t)r * WW + col;
            float4 v1 = __ldg((const float4*)(p1 + goff));
            float4 v2 = __ldg((const float4*)(p1 + X2OFF + goff));
            *((float4*)&x1s[row * WW  + col])      = v1;
            *((float4*)&x2s[row * X2W + 24 + col]) = v2;
        }
        __syncthreads();
        // ---- compute
        #pragma unroll
        for (int c = 0; c < CK; c++) {
            const int row = c * ROWSK + rr;
            float4 a = *((const float4*)&x1s[row * WW + w0]);
            float v[28];
            const float4* r2 = (const float4*)&x2s[row * X2W + w0]; // padded idx w0 .. w0+27
            #pragma unroll
            for (int m = 0; m < 7; m++) ((float4*)v)[m] = r2[m];
            #pragma unroll
            for (int i = 0; i < DD; i++) {
                acc[i].x = fmaf(a.x, v[24 - i], acc[i].x);
                acc[i].y = fmaf(a.y, v[25 - i], acc[i].y);
                acc[i].z = fmaf(a.z, v[26 - i], acc[i].z);
                acc[i].w = fmaf(a.w, v[27 - i], acc[i].w);
            }
        }
    }

    // ---- write corr[b][i][h0+rr][w0..w0+3]
    size_t obase = (size_t)b * DD * HWs + (size_t)(h0 + rr) * WW + w0;
    #pragma unroll
    for (int i = 0; i < DD; i++)
        *((float4*)(g_corr + obase + (size_t)i * HWs)) = acc[i];
}

// ---------------- kernel 2: per-plane 3x3 box sum (zero padded) ----------------
#define TILE_H 16
#define TPB2   256

__global__ __launch_bounds__(TPB2)
void box_kernel(float* __restrict__ out) {
    __shared__ float s[(TILE_H + 2) * (WW + 2)];   // 18*194*4 = 14 KB

    const int plane = blockIdx.y;    // b*25 + d  (0..399)
    const int tile  = blockIdx.x;    // 0..3
    const int t = threadIdx.x;

    const float* cp = g_corr + (size_t)plane * HWs;

    for (int idx = t; idx < (TILE_H + 2) * (WW + 2); idx += TPB2) {
        int hh = idx / (WW + 2);
        int ww = idx - hh * (WW + 2);
        int h = tile * TILE_H + hh - 1;
        int w = ww - 1;
        float v = 0.0f;
        if (h >= 0 && h < HH && w >= 0 && w < WW) v = cp[h * WW + w];
        s[idx] = v;
    }
    __syncthreads();

    float* op = out + (size_t)plane * HWs + (size_t)tile * TILE_H * WW;
    for (int idx = t; idx < TILE_H * WW; idx += TPB2) {
        int h = idx / WW;
        int w = idx - h * WW;
        const float* p = &s[h * (WW + 2) + w];
        float sum = p[0]       + p[1]       + p[2]
                  + p[WW + 2]  + p[WW + 3]  + p[WW + 4]
                  + p[2*WW + 4]+ p[2*WW + 5]+ p[2*WW + 6];
        op[idx] = sum;
    }
}

extern "C" void kernel_launch(void* const* d_in, const int* in_sizes, int n_in,
                              void* d_out, int out_size) {
    const float* in = (const float*)d_in[0];
    float* out = (float*)d_out;

    dim3 g1(HH / ROWSK, BB);      // (16, 16)
    corr_kernel<<<g1, TPB1>>>(in);

    dim3 g2(HH / TILE_H, BB * DD); // (4, 400)
    box_kernel<<<g2, TPB2>>>(out);
}

// round 2
// speedup vs baseline: 1.3547x; 1.3547x over previous
#include <cuda_runtime.h>

// Problem constants
#define BB   16
#define CC   256      // channels per image (input has 2*CC)
#define HH   64
#define WW   192
#define DD   25       // disparities 0..24
#define HWs  (HH*WW)              // 12288
#define CHW  (512*HH*WW)          // per-batch input stride
#define X2OFF ((size_t)CC*HWs)    // offset from x1 to x2

// corr tiling
#define CK    4       // channels per smem chunk
#define ROWSK 4       // h-rows per block
#define TPB1  192
#define NROWS (CK*ROWSK)          // 16 smem rows per buffer
#define X2W   (WW+24)             // 216: 24-col left zero pad

// scratch: corr[b][d][h][w]
__device__ float g_corr[(size_t)BB*DD*HH*WW];

__device__ __forceinline__ void cp_async16(float* dst, const float* src) {
    unsigned d = (unsigned)__cvta_generic_to_shared(dst);
    asm volatile("cp.async.cg.shared.global [%0], [%1], 16;\n" :: "r"(d), "l"(src));
}

__global__ __launch_bounds__(TPB1, 2)
void corr_kernel(const float* __restrict__ in) {
    __shared__ float x2s[2][NROWS * X2W];   // 2 * 13.5 KB

    const int t  = threadIdx.x;
    const int b  = blockIdx.y;
    const int h0 = blockIdx.x * ROWSK;
    const int rr = t / 48;
    const int j  = t - rr * 48;
    const int w0 = 4 * j;

    // zero the 24-col left pads of both buffers (never overwritten)
    for (int idx = t; idx < 2 * NROWS * 24; idx += TPB1) {
        int bu  = idx / (NROWS * 24);
        int rem = idx - bu * NROWS * 24;
        int row = rem / 24;
        int col = rem - row * 24;
        x2s[bu][row * X2W + col] = 0.0f;
    }

    const float* base   = in + (size_t)b * CHW + (size_t)h0 * WW;
    const float* x2base = base + X2OFF;

#define ISSUE_CHUNK(buf, ch) do {                                              \
    const float* p2 = x2base + (size_t)(ch) * CK * HWs;                        \
    _Pragma("unroll")                                                          \
    for (int it = 0; it < 4; it++) {                                           \
        int q   = it * TPB1 + t;                                               \
        int row = q / 48;                                                      \
        int col = (q - row * 48) * 4;                                          \
        int cl  = row >> 2;                                                    \
        int r   = row & 3;                                                     \
        cp_async16(&x2s[buf][row * X2W + 24 + col],                            \
                   p2 + (size_t)cl * HWs + (size_t)r * WW + col);              \
    }                                                                          \
    asm volatile("cp.async.commit_group;\n");                                  \
} while (0)

    float4 acc[DD];
    #pragma unroll
    for (int i = 0; i < DD; i++) acc[i] = make_float4(0.f, 0.f, 0.f, 0.f);

    // x1 is exclusive per thread: direct coalesced LDG with depth-2 prefetch ring
    const float* x1p = in + (size_t)b * CHW + (size_t)(h0 + rr) * WW + w0;
    float4 xp0 = __ldg((const float4*)x1p);
    float4 xp1 = __ldg((const float4*)(x1p + HWs));
    const float* x1n = x1p + 2 * (size_t)HWs;   // reads past c=255 stay inside input (x2 region), unused

    ISSUE_CHUNK(0, 0);

    for (int ch = 0; ch < CC / CK; ch++) {
        asm volatile("cp.async.wait_group 0;\n");
        __syncthreads();                         // chunk ch visible; chunk ch-1 compute done everywhere
        if (ch + 1 < CC / CK) ISSUE_CHUNK((ch + 1) & 1, ch + 1);

        const float* xr = &x2s[ch & 1][0];
        #pragma unroll
        for (int cl = 0; cl < CK; cl++) {
            float4 a = xp0; xp0 = xp1;
            xp1 = __ldg((const float4*)x1n); x1n += HWs;

            float v[28];
            const float4* r2 = (const float4*)(xr + (cl * ROWSK + rr) * X2W + w0);
            #pragma unroll
            for (int m = 0; m < 7; m++) ((float4*)v)[m] = r2[m];
            #pragma unroll
            for (int i = 0; i < DD; i++) {
                acc[i].x = fmaf(a.x, v[24 - i], acc[i].x);
                acc[i].y = fmaf(a.y, v[25 - i], acc[i].y);
                acc[i].z = fmaf(a.z, v[26 - i], acc[i].z);
                acc[i].w = fmaf(a.w, v[27 - i], acc[i].w);
            }
        }
    }

    size_t obase = (size_t)b * DD * HWs + (size_t)(h0 + rr) * WW + w0;
    #pragma unroll
    for (int i = 0; i < DD; i++)
        *((float4*)(g_corr + obase + (size_t)i * HWs)) = acc[i];
#undef ISSUE_CHUNK
}

// ---------------- kernel 2: per-plane 3x3 box sum (zero padded) ----------------
#define TPB2 192

__global__ __launch_bounds__(TPB2)
void box_kernel(float* __restrict__ out) {
    __shared__ float vs[2][WW + 2];

    const int w     = threadIdx.x;          // one w column per thread
    const int plane = blockIdx.x;            // b*25 + d
    const int h0    = blockIdx.y * 32;

    const float* cp = g_corr + (size_t)plane * HWs;
    float*       op = out    + (size_t)plane * HWs;

    if (w == 0) { vs[0][0] = 0.f; vs[0][WW + 1] = 0.f; vs[1][0] = 0.f; vs[1][WW + 1] = 0.f; }

    float a  = (h0 > 0) ? cp[(h0 - 1) * WW + w] : 0.f;
    float bz = cp[h0 * WW + w];
    float c  = cp[(h0 + 1) * WW + w];        // h0+1 <= 33 < 64 always valid

    for (int r = 0; r < 32; r++) {
        int hn = h0 + r + 2;
        float cn = (hn < HH) ? cp[hn * WW + w] : 0.f;   // prefetch next row
        vs[r & 1][w + 1] = a + bz + c;
        __syncthreads();
        const float* s = vs[r & 1];
        op[(h0 + r) * WW + w] = s[w] + s[w + 1] + s[w + 2];
        a = bz; bz = c; c = cn;
    }
}

extern "C" void kernel_launch(void* const* d_in, const int* in_sizes, int n_in,
                              void* d_out, int out_size) {
    const float* in = (const float*)d_in[0];
    float* out = (float*)d_out;

    dim3 g1(HH / ROWSK, BB);      // (16, 16) = 256 blocks
    corr_kernel<<<g1, TPB1>>>(in);

    dim3 g2(BB * DD, 2);          // (400, 2) = 800 blocks
    box_kernel<<<g2, TPB2>>>(out);
}